// round 14
// baseline (speedup 1.0000x reference)
#include <cuda_runtime.h>
#include <cuda_bf16.h>
#include <cstdint>

#define S_GRID 7
#define CH 30
#define TILE 1470          // 7*7*30 floats per image
#define MAXM 16
#define NUMC 20
#define IPB 8              // images per block
#define SLICE_BYTES (IPB * TILE * 4)   // 47040... no: 8*1470*4 = 47040 B
#define MAXPART 2048       // >= B/IPB

// NOTE: 8 images * 1470 floats * 4 B = 47040 B slice per block.
// smem budget: 47040 + small extras -> 4 blocks/SM (228KB/47KB), 16 warps/SM.
// To keep occupancy reasonable we stage at IPB=8 with 256 threads.

__device__ float g_partial[MAXPART];
__device__ unsigned int g_count = 0;

__device__ __forceinline__ uint32_t smem_u32(const void* p) {
    return (uint32_t)__cvta_generic_to_shared(p);
}

__device__ __forceinline__ float iou_fn(float a0, float a1, float a2, float a3,
                                        float b0, float b1, float b2, float b3) {
    float ax1 = a0 - a2 * 0.5f, ay1 = a1 - a3 * 0.5f;
    float ax2 = a0 + a2 * 0.5f, ay2 = a1 + a3 * 0.5f;
    float bx1 = b0 - b2 * 0.5f, by1 = b1 - b3 * 0.5f;
    float bx2 = b0 + b2 * 0.5f, by2 = b1 + b3 * 0.5f;
    float iw = fmaxf(fminf(ax2, bx2) - fmaxf(ax1, bx1), 0.0f);
    float ih = fmaxf(fminf(ay2, by2) - fmaxf(ay1, by1), 0.0f);
    float inter = iw * ih;
    float uni = a2 * a3 + b2 * b3 - inter;
    return inter / (uni + 1e-6f);
}

__device__ __forceinline__ float block_reduce_256(float v, float* s_red, int t) {
    #pragma unroll
    for (int off = 16; off > 0; off >>= 1)
        v += __shfl_down_sync(0xffffffffu, v, off);
    if ((t & 31) == 0) s_red[t >> 5] = v;
    __syncthreads();
    float r = 0.0f;
    #pragma unroll
    for (int i = 0; i < 8; i++) r += s_red[i];
    return r;
}

__global__ __launch_bounds__(256) void yolo_loss_tma(
    const float* __restrict__ pred,
    const float* __restrict__ gt_xywh,
    const int*   __restrict__ gt_class,
    float* __restrict__ out,
    int nblk, int Btot) {

    const int t = threadIdx.x;
    const long long b0 = (long long)blockIdx.x * IPB;

    __shared__ __align__(16) float s_tile[IPB * TILE];   // 47040 B
    __shared__ uint64_t s_mbar;
    __shared__ int s_cell[IPB][MAXM];
    __shared__ float s_red[8];
    __shared__ int s_last;

    const uint32_t mbar = smem_u32(&s_mbar);
    const uint32_t dstu = smem_u32(s_tile);

    // ---- init mbarrier, kick off one bulk copy of the whole slice ----
    if (t == 0) {
        asm volatile("mbarrier.init.shared.b64 [%0], 1;" :: "r"(mbar) : "memory");
    }
    __syncthreads();
    if (t == 0) {
        asm volatile("mbarrier.arrive.expect_tx.shared.b64 _, [%0], %1;"
                     :: "r"(mbar), "r"((uint32_t)(IPB * TILE * 4)) : "memory");
        asm volatile(
            "cp.async.bulk.shared::cta.global.mbarrier::complete_tx::bytes "
            "[%0], [%1], %2, [%3];"
            :: "r"(dstu), "l"(pred + b0 * TILE),
               "r"((uint32_t)(IPB * TILE * 4)), "r"(mbar) : "memory");
    }

    // ---- overlap: gt metadata (8 imgs x 16 boxes = 128 slots; 256 threads,
    //      lower half does the work), coalesced float4 ----
    float4 g = make_float4(0.f, 0.f, 0.f, 0.f);
    int cls = 0, cell = 0, row = 0, col = 0;
    const int img = t >> 4;        // 0..7 valid for t<128
    const int m   = t & 15;
    if (t < 128) {
        g   = reinterpret_cast<const float4*>(gt_xywh)[(long long)blockIdx.x * 128 + t];
        cls = gt_class[(long long)blockIdx.x * 128 + t];
        // Faithful to reference: row from x, col from y.
        row = min(max((int)floorf(g.x * 7.0f), 0), S_GRID - 1);
        col = min(max((int)floorf(g.y * 7.0f), 0), S_GRID - 1);
        cell = row * S_GRID + col;
        s_cell[img][m] = cell;
    }
    __syncthreads();

    int keep = 0;
    if (t < 128) {
        keep = 1;
        for (int i = 0; i < m; i++)
            if (s_cell[img][i] == cell) keep = 0;
    }

    // ---- wait for TMA completion ----
    {
        uint32_t done;
        asm volatile(
            "{\n\t.reg .pred p;\n\t"
            "mbarrier.try_wait.parity.shared.b64 p, [%1], 0;\n\t"
            "selp.b32 %0, 1, 0, p;\n\t}"
            : "=r"(done) : "r"(mbar) : "memory");
        while (!done) {
            asm volatile(
                "{\n\t.reg .pred p;\n\t"
                "mbarrier.try_wait.parity.shared.b64 p, [%1], 0, 0x989680;\n\t"
                "selp.b32 %0, 1, 0, p;\n\t}"
                : "=r"(done) : "r"(mbar) : "memory");
        }
    }

    // ---- consume from smem ----
    float acc = 0.0f;

    // noobj: 784 slots over 256 threads (k<3, plus t<16 extra); all-slots sum,
    // object-cell conf^2 subtracted by kept threads below.
    {
        float ssum = 0.0f;
        #pragma unroll
        for (int k = 0; k < 3; k++) {
            int idx = t + 256 * k;
            int i  = idx / 98;
            int r  = idx - i * 98;
            float v = s_tile[i * TILE + (r >> 1) * CH + ((r & 1) ? 9 : 4)];
            ssum += v * v;
        }
        if (t < 16) {
            int idx = t + 768;
            int i  = idx / 98;
            int r  = idx - i * 98;
            float v = s_tile[i * TILE + (r >> 1) * CH + ((r & 1) ? 9 : 4)];
            ssum += v * v;
        }
        acc += 0.5f * ssum;                          // LAMBDA_NOOBJ
    }

    if (keep) {
        const float2* rp = reinterpret_cast<const float2*>(
            &s_tile[img * TILE + cell * CH]);        // 8B-aligned
        float2 v0 = rp[0], v1 = rp[1], v2 = rp[2], v3 = rp[3], v4 = rp[4];

        acc -= 0.5f * (v2.x * v2.x + v4.y * v4.y);   // remove object-cell conf^2

        float tx = g.x * 7.0f - (float)col;          // faithful x/y swap
        float ty = g.y * 7.0f - (float)row;
        float tw = sqrtf(g.z);
        float th = sqrtf(g.w);

        float i1 = iou_fn(v0.x, v0.y, v1.x, v1.y, tx, ty, tw, th);
        float i2 = iou_fn(v2.y, v3.x, v3.y, v4.x, tx, ty, tw, th);
        bool use2 = (i2 >= i1);
        float bx = use2 ? v2.y : v0.x;
        float by = use2 ? v3.x : v0.y;
        float bw = use2 ? v3.y : v1.x;
        float bh = use2 ? v4.x : v1.y;
        float sc = use2 ? v4.y : v2.x;
        float si = use2 ? i2   : i1;

        float d0 = bx - tx, d1 = by - ty, d2 = bw - tw, d3 = bh - th;
        acc += 5.0f * (d0 * d0 + d1 * d1 + d2 * d2 + d3 * d3);  // LAMBDA_COORD
        float dc = sc - si;
        acc += dc * dc;

        #pragma unroll
        for (int i = 0; i < 10; i++) {
            float2 v = rp[5 + i];
            float e0 = v.x - ((2 * i     == cls) ? 1.0f : 0.0f);
            float e1 = v.y - ((2 * i + 1 == cls) ? 1.0f : 0.0f);
            acc += e0 * e0 + e1 * e1;
        }
    }

    // ---- block partial (spread stores) ----
    float tot = block_reduce_256(acc, s_red, t);
    if (t == 0) g_partial[blockIdx.x] = tot;

    // ---- fused final reduction: last block finishes ----
    __threadfence();
    if (t == 0) {
        unsigned int ticket = atomicAdd(&g_count, 1u);
        s_last = (ticket == (unsigned int)(nblk - 1));
    }
    __syncthreads();
    if (s_last) {
        __threadfence();
        float s = 0.0f;
        for (int i = t; i < nblk; i += 256)
            s += __ldcg(&g_partial[i]);
        __syncthreads();
        float fin = block_reduce_256(s, s_red, t);
        if (t == 0) {
            out[0] = fin / (float)Btot;
            g_count = 0;
        }
    }
}

extern "C" void kernel_launch(void* const* d_in, const int* in_sizes, int n_in,
                              void* d_out, int out_size) {
    const float* pred    = (const float*)d_in[0];
    const float* gt_xywh = (const float*)d_in[1];
    const int*   gt_cls  = (const int*)d_in[2];
    float* out = (float*)d_out;

    int B = in_sizes[0] / TILE;     // 16384
    int nblk = B / IPB;             // 2048

    yolo_loss_tma<<<nblk, 256>>>(pred, gt_xywh, gt_cls, out, nblk, B);
}

// round 15
// speedup vs baseline: 1.1235x; 1.1235x over previous
#include <cuda_runtime.h>
#include <cuda_bf16.h>

#define S_GRID 7
#define CH 30
#define TILE 1470          // 7*7*30
#define MAXM 16
#define NUMC 20
#define IPB 8              // images per slice
#define NITER 2            // slices per block
#define PHYS 1024          // physical blocks (all co-resident; 2048 slices total)

__device__ float g_partial[PHYS];
__device__ unsigned int g_count = 0;

__device__ __forceinline__ float iou_fn(float a0, float a1, float a2, float a3,
                                        float b0, float b1, float b2, float b3) {
    float ax1 = a0 - a2 * 0.5f, ay1 = a1 - a3 * 0.5f;
    float ax2 = a0 + a2 * 0.5f, ay2 = a1 + a3 * 0.5f;
    float bx1 = b0 - b2 * 0.5f, by1 = b1 - b3 * 0.5f;
    float bx2 = b0 + b2 * 0.5f, by2 = b1 + b3 * 0.5f;
    float iw = fmaxf(fminf(ax2, bx2) - fmaxf(ax1, bx1), 0.0f);
    float ih = fmaxf(fminf(ay2, by2) - fmaxf(ay1, by1), 0.0f);
    float inter = iw * ih;
    float uni = a2 * a3 + b2 * b3 - inter;
    return inter / (uni + 1e-6f);
}

__device__ __forceinline__ float block_reduce_128(float v, float* s_red, int t) {
    #pragma unroll
    for (int off = 16; off > 0; off >>= 1)
        v += __shfl_down_sync(0xffffffffu, v, off);
    if ((t & 31) == 0) s_red[t >> 5] = v;
    __syncthreads();
    return s_red[0] + s_red[1] + s_red[2] + s_red[3];
}

__global__ __launch_bounds__(128) void yolo_loss_persist(
    const float* __restrict__ pred,
    const float* __restrict__ gt_xywh,
    const int*   __restrict__ gt_class,
    float* __restrict__ out,
    int Btot) {

    const int t = threadIdx.x;
    const int img = t >> 4;        // 0..7
    const int m   = t & 15;        // 0..15

    __shared__ int s_cell[IPB][MAXM];
    __shared__ float s_red[4];
    __shared__ int s_last;

    float acc = 0.0f;

    #pragma unroll
    for (int it = 0; it < NITER; it++) {
        const int slice = blockIdx.x + it * PHYS;
        const long long b0 = (long long)slice * IPB;
        const float* base = pred + b0 * TILE;

        // ---- gt metadata: one box per thread (8 imgs x 16), coalesced ----
        float4 g = reinterpret_cast<const float4*>(gt_xywh)[(long long)slice * 128 + t];
        int cls  = gt_class[(long long)slice * 128 + t];
        // Faithful to reference: row from x, col from y.
        int row = min(max((int)floorf(g.x * 7.0f), 0), S_GRID - 1);
        int col = min(max((int)floorf(g.y * 7.0f), 0), S_GRID - 1);
        int cell = row * S_GRID + col;
        s_cell[img][m] = cell;

        // ---- noobj scatter loads: independent, issue early for MLP ----
        float nv[6];
        #pragma unroll
        for (int k = 0; k < 6; k++) {
            int idx = t + 128 * k;
            int i  = idx / 98;
            int r  = idx - i * 98;
            nv[k] = __ldg(base + i * TILE + (r >> 1) * CH + ((r & 1) ? 9 : 4));
        }
        float nv6 = 0.0f;
        if (t < 16) {
            int idx = t + 768;
            int i  = idx / 98;
            int r  = idx - i * 98;
            nv6 = __ldg(base + i * TILE + (r >> 1) * CH + ((r & 1) ? 9 : 4));
        }
        __syncthreads();

        // first-occurrence-per-cell dedup
        int keep = 1;
        for (int i = 0; i < m; i++)
            if (s_cell[img][i] == cell) keep = 0;

        // ---- box header loads (kept threads) ----
        const float2* rp = reinterpret_cast<const float2*>(
            base + img * TILE + cell * CH);          // 8B-aligned row
        float2 v0, v1, v2, v3, v4;
        if (keep) {
            v0 = __ldg(&rp[0]);   // ch0,1
            v1 = __ldg(&rp[1]);   // ch2,3
            v2 = __ldg(&rp[2]);   // ch4,5
            v3 = __ldg(&rp[3]);   // ch6,7
            v4 = __ldg(&rp[4]);   // ch8,9
        }

        // ---- consume ----
        float ssum = nv6 * nv6;
        #pragma unroll
        for (int k = 0; k < 6; k++)
            ssum += nv[k] * nv[k];
        acc += 0.5f * ssum;                          // LAMBDA_NOOBJ * all slots

        if (keep) {
            // subtract this distinct object cell's conf^2
            acc -= 0.5f * (v2.x * v2.x + v4.y * v4.y);

            float tx = g.x * 7.0f - (float)col;      // faithful x/y swap
            float ty = g.y * 7.0f - (float)row;
            float tw = sqrtf(g.z);
            float th = sqrtf(g.w);

            float i1 = iou_fn(v0.x, v0.y, v1.x, v1.y, tx, ty, tw, th);
            float i2 = iou_fn(v2.y, v3.x, v3.y, v4.x, tx, ty, tw, th);
            bool use2 = (i2 >= i1);
            float bx = use2 ? v2.y : v0.x;
            float by = use2 ? v3.x : v0.y;
            float bw = use2 ? v3.y : v1.x;
            float bh = use2 ? v4.x : v1.y;
            float sc = use2 ? v4.y : v2.x;
            float si = use2 ? i2   : i1;

            float d0 = bx - tx, d1 = by - ty, d2 = bw - tw, d3 = bh - th;
            acc += 5.0f * (d0 * d0 + d1 * d1 + d2 * d2 + d3 * d3);  // LAMBDA_COORD
            float dc = sc - si;
            acc += dc * dc;

            // classes ch10..29 in-loop: same L1 lines as v0..v4 (hits)
            #pragma unroll
            for (int i = 0; i < 10; i++) {
                float2 v = __ldg(&rp[5 + i]);
                float e0 = v.x - ((2 * i     == cls) ? 1.0f : 0.0f);
                float e1 = v.y - ((2 * i + 1 == cls) ? 1.0f : 0.0f);
                acc += e0 * e0 + e1 * e1;
            }
        }
        if (it + 1 < NITER) __syncthreads();   // protect s_cell reuse
    }

    // ---- block partial (spread stores, no contention) ----
    float tot = block_reduce_128(acc, s_red, t);
    if (t == 0) g_partial[blockIdx.x] = tot;

    // ---- fused final reduction: last block finishes ----
    __threadfence();
    if (t == 0) {
        unsigned int ticket = atomicAdd(&g_count, 1u);
        s_last = (ticket == (unsigned int)(PHYS - 1));
    }
    __syncthreads();
    if (s_last) {
        __threadfence();
        float s = 0.0f;
        for (int i = t; i < PHYS; i += 128)
            s += __ldcg(&g_partial[i]);
        __syncthreads();          // s_red reuse
        float fin = block_reduce_128(s, s_red, t);
        if (t == 0) {
            out[0] = fin / (float)Btot;
            g_count = 0;          // ready for next replay
        }
    }
}

extern "C" void kernel_launch(void* const* d_in, const int* in_sizes, int n_in,
                              void* d_out, int out_size) {
    const float* pred    = (const float*)d_in[0];
    const float* gt_xywh = (const float*)d_in[1];
    const int*   gt_cls  = (const int*)d_in[2];
    float* out = (float*)d_out;

    int B = in_sizes[0] / TILE;     // 16384

    yolo_loss_persist<<<PHYS, 128>>>(pred, gt_xywh, gt_cls, out, B);
}

// round 16
// speedup vs baseline: 1.2411x; 1.1047x over previous
#include <cuda_runtime.h>
#include <cuda_bf16.h>

#define S_GRID 7
#define CH 30
#define TILE 1470          // 7*7*30
#define MAXM 16
#define NUMC 20
#define IPB 8              // images per block
#define MAXPART 2048       // >= B/IPB

__device__ float g_partial[MAXPART];
__device__ unsigned int g_count = 0;

__device__ __forceinline__ float iou_fn(float a0, float a1, float a2, float a3,
                                        float b0, float b1, float b2, float b3) {
    float ax1 = a0 - a2 * 0.5f, ay1 = a1 - a3 * 0.5f;
    float ax2 = a0 + a2 * 0.5f, ay2 = a1 + a3 * 0.5f;
    float bx1 = b0 - b2 * 0.5f, by1 = b1 - b3 * 0.5f;
    float bx2 = b0 + b2 * 0.5f, by2 = b1 + b3 * 0.5f;
    float iw = fmaxf(fminf(ax2, bx2) - fmaxf(ax1, bx1), 0.0f);
    float ih = fmaxf(fminf(ay2, by2) - fmaxf(ay1, by1), 0.0f);
    float inter = iw * ih;
    float uni = a2 * a3 + b2 * b3 - inter;
    return inter / (uni + 1e-6f);
}

__device__ __forceinline__ float block_reduce_128(float v, float* s_red, int t) {
    #pragma unroll
    for (int off = 16; off > 0; off >>= 1)
        v += __shfl_down_sync(0xffffffffu, v, off);
    if ((t & 31) == 0) s_red[t >> 5] = v;
    __syncthreads();
    return s_red[0] + s_red[1] + s_red[2] + s_red[3];
}

__global__ __launch_bounds__(128) void yolo_loss_nobar(
    const float* __restrict__ pred,
    const float* __restrict__ gt_xywh,
    const int*   __restrict__ gt_class,
    float* __restrict__ out,
    int nblk, int Btot) {

    const int t = threadIdx.x;
    const long long b0 = (long long)blockIdx.x * IPB;
    const float* base = pred + b0 * TILE;

    __shared__ float s_red[4];
    __shared__ int s_last;

    // ---- gt metadata: one box per thread (8 imgs x 16 boxes), coalesced ----
    float4 g = reinterpret_cast<const float4*>(gt_xywh)[(long long)blockIdx.x * 128 + t];
    int cls  = gt_class[(long long)blockIdx.x * 128 + t];
    const int img = t >> 4;        // 0..7 (two images per warp: lanes 0-15, 16-31)
    // Faithful to reference: row from x, col from y.
    int row = min(max((int)floorf(g.x * 7.0f), 0), S_GRID - 1);
    int col = min(max((int)floorf(g.y * 7.0f), 0), S_GRID - 1);
    int cell = row * S_GRID + col;

    // ---- warp-local first-occurrence dedup (no smem, no barrier) ----
    const int lane = t & 31;
    const unsigned int halfmask = (lane < 16) ? 0x0000FFFFu : 0xFFFF0000u;
    unsigned int mm = __match_any_sync(0xffffffffu, cell) & halfmask;
    const int keep = ((mm & ((1u << lane) - 1u)) == 0u);

    // ---- noobj scatter loads: 784 slots, 6.1-deep per thread ----
    float nv[6];
    #pragma unroll
    for (int k = 0; k < 6; k++) {
        int idx = t + 128 * k;
        int i  = idx / 98;
        int r  = idx - i * 98;
        nv[k] = __ldg(base + i * TILE + (r >> 1) * CH + ((r & 1) ? 9 : 4));
    }
    float nv6 = 0.0f;
    if (t < 16) {
        int idx = t + 768;
        int i  = idx / 98;
        int r  = idx - i * 98;
        nv6 = __ldg(base + i * TILE + (r >> 1) * CH + ((r & 1) ? 9 : 4));
    }

    // ---- box header loads (kept threads), overlapped with noobj batch ----
    const float2* rp = reinterpret_cast<const float2*>(
        base + img * TILE + cell * CH);              // 8B-aligned row
    float2 v0, v1, v2, v3, v4;
    if (keep) {
        v0 = __ldg(&rp[0]);   // ch0,1
        v1 = __ldg(&rp[1]);   // ch2,3
        v2 = __ldg(&rp[2]);   // ch4,5
        v3 = __ldg(&rp[3]);   // ch6,7
        v4 = __ldg(&rp[4]);   // ch8,9
    }

    // ---- consume ----
    float acc = 0.0f;

    float ssum = nv6 * nv6;
    #pragma unroll
    for (int k = 0; k < 6; k++)
        ssum += nv[k] * nv[k];
    acc += 0.5f * ssum;                              // LAMBDA_NOOBJ * all slots

    if (keep) {
        // subtract this distinct object cell's conf^2 from the all-slots sum
        acc -= 0.5f * (v2.x * v2.x + v4.y * v4.y);

        float tx = g.x * 7.0f - (float)col;          // faithful x/y swap
        float ty = g.y * 7.0f - (float)row;
        float tw = sqrtf(g.z);
        float th = sqrtf(g.w);

        float i1 = iou_fn(v0.x, v0.y, v1.x, v1.y, tx, ty, tw, th);
        float i2 = iou_fn(v2.y, v3.x, v3.y, v4.x, tx, ty, tw, th);
        bool use2 = (i2 >= i1);
        float bx = use2 ? v2.y : v0.x;
        float by = use2 ? v3.x : v0.y;
        float bw = use2 ? v3.y : v1.x;
        float bh = use2 ? v4.x : v1.y;
        float sc = use2 ? v4.y : v2.x;
        float si = use2 ? i2   : i1;

        float d0 = bx - tx, d1 = by - ty, d2 = bw - tw, d3 = bh - th;
        acc += 5.0f * (d0 * d0 + d1 * d1 + d2 * d2 + d3 * d3);  // LAMBDA_COORD
        float dc = sc - si;
        acc += dc * dc;

        // classes ch10..29: same L1 lines as v0..v4 (hits), in-loop saves regs
        #pragma unroll
        for (int i = 0; i < 10; i++) {
            float2 v = __ldg(&rp[5 + i]);
            float e0 = v.x - ((2 * i     == cls) ? 1.0f : 0.0f);
            float e1 = v.y - ((2 * i + 1 == cls) ? 1.0f : 0.0f);
            acc += e0 * e0 + e1 * e1;
        }
    }

    // ---- block partial (spread stores, no contention) ----
    float tot = block_reduce_128(acc, s_red, t);
    if (t == 0) g_partial[blockIdx.x] = tot;

    // ---- fused final reduction: last block finishes ----
    __threadfence();
    if (t == 0) {
        unsigned int ticket = atomicAdd(&g_count, 1u);
        s_last = (ticket == (unsigned int)(nblk - 1));
    }
    __syncthreads();
    if (s_last) {
        __threadfence();
        float s = 0.0f;
        for (int i = t; i < nblk; i += 128)
            s += __ldcg(&g_partial[i]);
        __syncthreads();          // s_red reuse
        float fin = block_reduce_128(s, s_red, t);
        if (t == 0) {
            out[0] = fin / (float)Btot;
            g_count = 0;          // ready for next replay
        }
    }
}

extern "C" void kernel_launch(void* const* d_in, const int* in_sizes, int n_in,
                              void* d_out, int out_size) {
    const float* pred    = (const float*)d_in[0];
    const float* gt_xywh = (const float*)d_in[1];
    const int*   gt_cls  = (const int*)d_in[2];
    float* out = (float*)d_out;

    int B = in_sizes[0] / TILE;     // 16384
    int nblk = B / IPB;             // 2048

    yolo_loss_nobar<<<nblk, 128>>>(pred, gt_xywh, gt_cls, out, nblk, B);
}

// round 17
// speedup vs baseline: 1.2576x; 1.0133x over previous
#include <cuda_runtime.h>
#include <cuda_bf16.h>

#define S_GRID 7
#define CH 30
#define TILE 1470          // 7*7*30
#define MAXM 16
#define NUMC 20
#define IPB 4              // images per block
#define THREADS 64
#define MAXPART 4096       // >= B/IPB

__device__ float g_partial[MAXPART];
__device__ unsigned int g_count = 0;

__device__ __forceinline__ float iou_fn(float a0, float a1, float a2, float a3,
                                        float b0, float b1, float b2, float b3) {
    float ax1 = a0 - a2 * 0.5f, ay1 = a1 - a3 * 0.5f;
    float ax2 = a0 + a2 * 0.5f, ay2 = a1 + a3 * 0.5f;
    float bx1 = b0 - b2 * 0.5f, by1 = b1 - b3 * 0.5f;
    float bx2 = b0 + b2 * 0.5f, by2 = b1 + b3 * 0.5f;
    float iw = fmaxf(fminf(ax2, bx2) - fmaxf(ax1, bx1), 0.0f);
    float ih = fmaxf(fminf(ay2, by2) - fmaxf(ay1, by1), 0.0f);
    float inter = iw * ih;
    float uni = a2 * a3 + b2 * b3 - inter;
    return inter / (uni + 1e-6f);
}

__device__ __forceinline__ float block_reduce_64(float v, float* s_red, int t) {
    #pragma unroll
    for (int off = 16; off > 0; off >>= 1)
        v += __shfl_down_sync(0xffffffffu, v, off);
    if ((t & 31) == 0) s_red[t >> 5] = v;
    __syncthreads();
    return s_red[0] + s_red[1];
}

__global__ __launch_bounds__(THREADS) void yolo_loss_small(
    const float* __restrict__ pred,
    const float* __restrict__ gt_xywh,
    const int*   __restrict__ gt_class,
    float* __restrict__ out,
    int nblk, int Btot) {

    const int t = threadIdx.x;
    const long long b0 = (long long)blockIdx.x * IPB;
    const float* base = pred + b0 * TILE;

    __shared__ float s_red[2];
    __shared__ int s_last;

    // ---- gt metadata: one box per thread (4 imgs x 16 boxes), coalesced ----
    float4 g = reinterpret_cast<const float4*>(gt_xywh)[(long long)blockIdx.x * THREADS + t];
    int cls  = gt_class[(long long)blockIdx.x * THREADS + t];
    const int img = t >> 4;        // 0..3 (one image per half-warp)
    // Faithful to reference: row from x, col from y.
    int row = min(max((int)floorf(g.x * 7.0f), 0), S_GRID - 1);
    int col = min(max((int)floorf(g.y * 7.0f), 0), S_GRID - 1);
    int cell = row * S_GRID + col;

    // ---- warp-local first-occurrence dedup (one image per half-warp) ----
    const int lane = t & 31;
    const unsigned int halfmask = (lane < 16) ? 0x0000FFFFu : 0xFFFF0000u;
    unsigned int mm = __match_any_sync(0xffffffffu, cell) & halfmask;
    const int keep = ((mm & ((1u << lane) - 1u)) == 0u);

    // ---- noobj scatter loads: 4 imgs x 98 = 392 slots, 6.125-deep ----
    float nv[6];
    #pragma unroll
    for (int k = 0; k < 6; k++) {
        int idx = t + THREADS * k;
        int i  = idx / 98;
        int r  = idx - i * 98;
        nv[k] = __ldg(base + i * TILE + (r >> 1) * CH + ((r & 1) ? 9 : 4));
    }
    float nv6 = 0.0f;
    if (t < 8) {
        int idx = t + 384;
        int i  = idx / 98;
        int r  = idx - i * 98;
        nv6 = __ldg(base + i * TILE + (r >> 1) * CH + ((r & 1) ? 9 : 4));
    }

    // ---- box header loads (kept threads), overlapped with noobj batch ----
    const float2* rp = reinterpret_cast<const float2*>(
        base + img * TILE + cell * CH);              // 8B-aligned row
    float2 v0, v1, v2, v3, v4;
    if (keep) {
        v0 = __ldg(&rp[0]);   // ch0,1
        v1 = __ldg(&rp[1]);   // ch2,3
        v2 = __ldg(&rp[2]);   // ch4,5
        v3 = __ldg(&rp[3]);   // ch6,7
        v4 = __ldg(&rp[4]);   // ch8,9
    }

    // ---- consume ----
    float acc = 0.0f;

    float ssum = nv6 * nv6;
    #pragma unroll
    for (int k = 0; k < 6; k++)
        ssum += nv[k] * nv[k];
    acc += 0.5f * ssum;                              // LAMBDA_NOOBJ * all slots

    if (keep) {
        // subtract this distinct object cell's conf^2 from the all-slots sum
        acc -= 0.5f * (v2.x * v2.x + v4.y * v4.y);

        float tx = g.x * 7.0f - (float)col;          // faithful x/y swap
        float ty = g.y * 7.0f - (float)row;
        float tw = sqrtf(g.z);
        float th = sqrtf(g.w);

        float i1 = iou_fn(v0.x, v0.y, v1.x, v1.y, tx, ty, tw, th);
        float i2 = iou_fn(v2.y, v3.x, v3.y, v4.x, tx, ty, tw, th);
        bool use2 = (i2 >= i1);
        float bx = use2 ? v2.y : v0.x;
        float by = use2 ? v3.x : v0.y;
        float bw = use2 ? v3.y : v1.x;
        float bh = use2 ? v4.x : v1.y;
        float sc = use2 ? v4.y : v2.x;
        float si = use2 ? i2   : i1;

        float d0 = bx - tx, d1 = by - ty, d2 = bw - tw, d3 = bh - th;
        acc += 5.0f * (d0 * d0 + d1 * d1 + d2 * d2 + d3 * d3);  // LAMBDA_COORD
        float dc = sc - si;
        acc += dc * dc;

        // classes ch10..29: same L1 lines as v0..v4 (hits), in-loop saves regs
        #pragma unroll
        for (int i = 0; i < 10; i++) {
            float2 v = __ldg(&rp[5 + i]);
            float e0 = v.x - ((2 * i     == cls) ? 1.0f : 0.0f);
            float e1 = v.y - ((2 * i + 1 == cls) ? 1.0f : 0.0f);
            acc += e0 * e0 + e1 * e1;
        }
    }

    // ---- block partial (spread stores, no contention) ----
    float tot = block_reduce_64(acc, s_red, t);
    if (t == 0) g_partial[blockIdx.x] = tot;

    // ---- fused final reduction: last block finishes ----
    __threadfence();
    if (t == 0) {
        unsigned int ticket = atomicAdd(&g_count, 1u);
        s_last = (ticket == (unsigned int)(nblk - 1));
    }
    __syncthreads();
    if (s_last) {
        __threadfence();
        float s = 0.0f;
        for (int i = t; i < nblk; i += THREADS)
            s += __ldcg(&g_partial[i]);
        __syncthreads();          // s_red reuse
        float fin = block_reduce_64(s, s_red, t);
        if (t == 0) {
            out[0] = fin / (float)Btot;
            g_count = 0;          // ready for next replay
        }
    }
}

extern "C" void kernel_launch(void* const* d_in, const int* in_sizes, int n_in,
                              void* d_out, int out_size) {
    const float* pred    = (const float*)d_in[0];
    const float* gt_xywh = (const float*)d_in[1];
    const int*   gt_cls  = (const int*)d_in[2];
    float* out = (float*)d_out;

    int B = in_sizes[0] / TILE;     // 16384
    int nblk = B / IPB;             // 4096

    yolo_loss_small<<<nblk, THREADS>>>(pred, gt_xywh, gt_cls, out, nblk, B);
}